// round 12
// baseline (speedup 1.0000x reference)
#include <cuda_runtime.h>
#include <cuda_fp16.h>

// M is 2000 x 20000 fp32 (fixed by setup_inputs).
#define Nn 2000
#define Mm 20000
#define ALPHA 20.0f
#define THR 0.005f
#define EPSc 1e-16f
#define NT 1024
#define NBLK 148                 // one block per SM (co-resident by construction)
#define A_TASKS 1000             // 100 row-chunks (20 rows) x 10 col-strips (2000)
#define EX3 452                  // leftover uint4 col-slots: 2500 - 2048

// Static device scratch (no runtime allocation).
__device__ __half g_he[(size_t)Nn * Mm];    // exp(-20 M) fp16: 80 MB
__device__ float g_v[Mm];
__device__ float g_PA[(size_t)100 * Mm];    // pass-1 column partials (8 MB)
__device__ float g_C[(size_t)NBLK * Mm];    // per-block K^T u partials (11.8 MB)
__device__ float g_errP[NBLK];
__device__ float g_lossP[NBLK];
__device__ unsigned g_ticket = 0;
__device__ unsigned g_barcnt = 0;

__device__ __forceinline__ unsigned ldcg_u(const unsigned* p) {
    unsigned v;
    asm volatile("ld.global.cg.u32 %0, [%1];" : "=r"(v) : "l"(p));
    return v;
}

// Grid barrier: one arrival atomic per block, plain-L2-load polling.
__device__ __forceinline__ void gridbar(unsigned* eps) {
    __syncthreads();
    if (threadIdx.x == 0) {
        unsigned target = *eps + NBLK;
        __threadfence();                        // release
        atomicAdd(&g_barcnt, 1u);
        while (ldcg_u(&g_barcnt) < target) __nanosleep(64);
        __threadfence();                        // acquire
        *eps = target;
    }
    __syncthreads();
}

__device__ __forceinline__ void unpack8(const uint4& h, float* e) {
    float2 p0 = __half22float2(*(const __half2*)&h.x);
    float2 p1 = __half22float2(*(const __half2*)&h.y);
    float2 p2 = __half22float2(*(const __half2*)&h.z);
    float2 p3 = __half22float2(*(const __half2*)&h.w);
    e[0] = p0.x; e[1] = p0.y; e[2] = p1.x; e[3] = p1.y;
    e[4] = p2.x; e[5] = p2.y; e[6] = p3.x; e[7] = p3.y;
}

__global__ void __launch_bounds__(NT, 1)
sinkhorn_all(const float* __restrict__ M, float* __restrict__ out) {
    const int tid = threadIdx.x, bid = blockIdx.x;
    const int tx = tid & 31, ty = tid >> 5;
    // merge/combine column strip: 20 blocks x 136 + 128 x 135 = 20000
    const int js = bid * 135 + min(bid, 20);
    const int w  = 135 + (bid < 20 ? 1 : 0);
    // fused-pass rows: 76 blocks x 14 + 72 x 13 = 2000
    const int rs = bid * 13 + min(bid, 76);
    const int re = rs + 13 + (bid < 76 ? 1 : 0);

    __shared__ float s_red[2][2000];            // 16 KB (pass 1)
    __shared__ float s_wS[32], s_wL[32];
    __shared__ float sv3[8][EX3];               // 14.1 KB
    __shared__ float sC3[8][EX3];               // 14.1 KB
    __shared__ float s_bc;
    __shared__ int s_cur, s_next;
    __shared__ unsigned s_ep;

    if (tid == 0) s_ep = 0;
    __syncthreads();
    const float bm = 1.0f / (float)Mm;
    const float am = 1.0f / (float)Nn;

    // ---- Pass 1: colsum(e); stream M (__ldcs) and write he (fp16). ----
    const int cg = tid % 500, rg = tid / 500;
    if (tid == 0) s_cur = (int)atomicAdd(&g_ticket, 1u);
    __syncthreads();
    int cur = s_cur;
    while (cur < A_TASKS) {
        if (tid == 1023) s_next = (int)atomicAdd(&g_ticket, 1u);
        const int chunk = cur / 10, strip = cur - chunk * 10;
        if (tid < 1000) {
            const int j = strip * 2000 + cg * 4;
            const int r0 = chunk * 20 + rg * 10;
            const float4* Mp = (const float4*)(M + (size_t)r0 * Mm + j);
            __half* Hp = g_he + (size_t)r0 * Mm + j;
            float a0 = 0.f, a1 = 0.f, a2 = 0.f, a3 = 0.f;
            #pragma unroll
            for (int kk = 0; kk < 10; ++kk) {
                float4 m4 = __ldcs(Mp + (size_t)kk * (Mm / 4));
                float e0 = __expf(-ALPHA * m4.x);
                float e1 = __expf(-ALPHA * m4.y);
                float e2 = __expf(-ALPHA * m4.z);
                float e3 = __expf(-ALPHA * m4.w);
                a0 += e0; a1 += e1; a2 += e2; a3 += e3;
                uint2 hv;
                *(__half2*)&hv.x = __floats2half2_rn(e0, e1);
                *(__half2*)&hv.y = __floats2half2_rn(e2, e3);
                *(uint2*)(Hp + (size_t)kk * Mm) = hv;
            }
            s_red[rg][cg * 4]     = a0;
            s_red[rg][cg * 4 + 1] = a1;
            s_red[rg][cg * 4 + 2] = a2;
            s_red[rg][cg * 4 + 3] = a3;
        }
        __syncthreads();
        if (tid < 1000) {
            const size_t base = (size_t)chunk * Mm + strip * 2000;
            g_PA[base + tid]        = s_red[0][tid] + s_red[1][tid];
            g_PA[base + tid + 1000] = s_red[0][tid + 1000] + s_red[1][tid + 1000];
        }
        cur = s_next;
        __syncthreads();
    }
    gridbar(&s_ep);

    // ---- Combine: v1[j] = bm / (colsum*am + eps) on this block's strip.
    //      Loop bound is warp-UNIFORM (136); invalid lanes are predicated
    //      but still participate in the width-8 shuffles. ----
    {
        const int p = tid & 7;
        for (int cl = tid >> 3; cl < 136; cl += 128) {
            const bool valid = (cl < w);
            const int j = js + (valid ? cl : 0);
            float T = 0.f;
            if (valid) {
                for (int ch = p; ch < 100; ch += 8)
                    T += __ldcg(&g_PA[(size_t)ch * Mm + j]);
            }
            T += __shfl_down_sync(0xffffffffu, T, 4, 8);
            T += __shfl_down_sync(0xffffffffu, T, 2, 8);
            T += __shfl_down_sync(0xffffffffu, T, 1, 8);
            if (p == 0 && valid) g_v[j] = bm / (T * am + EPSc);
        }
    }
    gridbar(&s_ep);

    // Reference: err only updated at cpt==1 / cpt==51 -> exit only at cpt in
    // {1,51,100}. Fused pass k: u_k = a/(K v_k + eps) per row; C = per-block
    // K^T u_k partials (same he row, register-resident); loss integrand when
    // k in {1,51,100}. Merge: T_j, err(cpt=k), v_{k+1}.
    bool done = false;
    for (int k = 1; k <= 100 && !done; ++k) {
        const bool chk = (k == 1) || (k == 51);
        const bool lossk = chk || (k == 100);

        // Stage v into registers (slots tid, tid+1024) and shared (slot3).
        float va[8], vb[8];
        {
            const float* vp1 = g_v + 8 * tid;
            float4 t0 = __ldcg((const float4*)vp1);
            float4 t1 = __ldcg((const float4*)(vp1 + 4));
            va[0]=t0.x; va[1]=t0.y; va[2]=t0.z; va[3]=t0.w;
            va[4]=t1.x; va[5]=t1.y; va[6]=t1.z; va[7]=t1.w;
            const float* vp2 = g_v + 8 * (tid + 1024);
            float4 t2 = __ldcg((const float4*)vp2);
            float4 t3 = __ldcg((const float4*)(vp2 + 4));
            vb[0]=t2.x; vb[1]=t2.y; vb[2]=t2.z; vb[3]=t2.w;
            vb[4]=t3.x; vb[5]=t3.y; vb[6]=t3.z; vb[7]=t3.w;
        }
        if (tid < EX3) {
            const float* vp3 = g_v + 8 * (tid + 2048);
            float4 t0 = __ldcg((const float4*)vp3);
            float4 t1 = __ldcg((const float4*)(vp3 + 4));
            sv3[0][tid]=t0.x; sv3[1][tid]=t0.y; sv3[2][tid]=t0.z; sv3[3][tid]=t0.w;
            sv3[4][tid]=t1.x; sv3[5][tid]=t1.y; sv3[6][tid]=t1.z; sv3[7][tid]=t1.w;
            #pragma unroll
            for (int q = 0; q < 8; ++q) sC3[q][tid] = 0.f;
        }
        float C1[8], C2[8];
        #pragma unroll
        for (int q = 0; q < 8; ++q) { C1[q] = 0.f; C2[q] = 0.f; }
        float loss_acc = 0.f;
        __syncthreads();

        for (int r = rs; r < re; ++r) {
            const __half* hp = g_he + (size_t)r * Mm;
            uint4 h1 = *(const uint4*)(hp + 8 * tid);          // he is read-only
            uint4 h2 = *(const uint4*)(hp + 8 * (tid + 1024)); // after pass 1
            uint4 h3;
            if (tid < EX3) h3 = *(const uint4*)(hp + 8 * (tid + 2048));
            float S = 0.f, L = 0.f;
            {
                float e[8];
                unpack8(h1, e);
                #pragma unroll
                for (int q = 0; q < 8; ++q) {
                    float p = e[q] * va[q];
                    S += p;
                    if (lossk) L += p * __logf(fmaxf(e[q], 1e-30f));
                }
                unpack8(h2, e);
                #pragma unroll
                for (int q = 0; q < 8; ++q) {
                    float p = e[q] * vb[q];
                    S += p;
                    if (lossk) L += p * __logf(fmaxf(e[q], 1e-30f));
                }
                if (tid < EX3) {
                    unpack8(h3, e);
                    #pragma unroll
                    for (int q = 0; q < 8; ++q) {
                        float p = e[q] * sv3[q][tid];
                        S += p;
                        if (lossk) L += p * __logf(fmaxf(e[q], 1e-30f));
                    }
                }
            }
            #pragma unroll
            for (int o = 16; o > 0; o >>= 1) {
                S += __shfl_xor_sync(0xffffffffu, S, o);
                if (lossk) L += __shfl_xor_sync(0xffffffffu, L, o);
            }
            if (tx == 0) { s_wS[ty] = S; if (lossk) s_wL[ty] = L; }
            __syncthreads();
            float Lrow = 0.f;
            if (ty == 0) {
                float Sv = s_wS[tx];
                #pragma unroll
                for (int o = 16; o > 0; o >>= 1)
                    Sv += __shfl_xor_sync(0xffffffffu, Sv, o);
                if (tx == 0) s_bc = am / (Sv + EPSc);
            }
            if (ty == 1 && lossk) {
                float Lv = s_wL[tx];
                #pragma unroll
                for (int o = 16; o > 0; o >>= 1)
                    Lv += __shfl_xor_sync(0xffffffffu, Lv, o);
                Lrow = Lv;
            }
            __syncthreads();
            const float u = s_bc;
            if (lossk && tid == 32) loss_acc += u * Lrow;
            {
                float e[8];
                unpack8(h1, e);
                #pragma unroll
                for (int q = 0; q < 8; ++q) C1[q] = fmaf(u, e[q], C1[q]);
                unpack8(h2, e);
                #pragma unroll
                for (int q = 0; q < 8; ++q) C2[q] = fmaf(u, e[q], C2[q]);
                if (tid < EX3) {
                    unpack8(h3, e);
                    #pragma unroll
                    for (int q = 0; q < 8; ++q)
                        sC3[q][tid] = fmaf(u, e[q], sC3[q][tid]);
                }
            }
        }
        // Write this block's K^T u partials.
        {
            float* cp = g_C + (size_t)bid * Mm;
            *(float4*)(cp + 8 * tid)     = make_float4(C1[0], C1[1], C1[2], C1[3]);
            *(float4*)(cp + 8 * tid + 4) = make_float4(C1[4], C1[5], C1[6], C1[7]);
            *(float4*)(cp + 8 * (tid + 1024))     = make_float4(C2[0], C2[1], C2[2], C2[3]);
            *(float4*)(cp + 8 * (tid + 1024) + 4) = make_float4(C2[4], C2[5], C2[6], C2[7]);
            if (tid < EX3) {
                *(float4*)(cp + 8 * (tid + 2048)) =
                    make_float4(sC3[0][tid], sC3[1][tid], sC3[2][tid], sC3[3][tid]);
                *(float4*)(cp + 8 * (tid + 2048) + 4) =
                    make_float4(sC3[4][tid], sC3[5][tid], sC3[6][tid], sC3[7][tid]);
            }
        }
        if (lossk && tid == 32) g_lossP[bid] = loss_acc;
        gridbar(&s_ep);

        if (k == 100) {                         // exit without convergence
            if (bid == 0) {
                float l = (tid < NBLK) ? __ldcg(&g_lossP[tid]) : 0.f;
                #pragma unroll
                for (int o = 16; o > 0; o >>= 1)
                    l += __shfl_xor_sync(0xffffffffu, l, o);
                if (tx == 0) s_wS[ty] = l;
                __syncthreads();
                if (ty == 0) {
                    float t2 = s_wS[tx];
                    #pragma unroll
                    for (int o = 16; o > 0; o >>= 1)
                        t2 += __shfl_xor_sync(0xffffffffu, t2, o);
                    if (tx == 0) out[0] = t2 * (-100.0f / ALPHA);
                }
            }
            done = true;
            continue;
        }

        // ---- Merge: T_j = sum_b C[b][j]; err at chk; v_{k+1}.
        //      Warp-uniform loop bound (136) + valid predicate: all lanes
        //      participate in the width-8 shuffles. ----
        float errA = 0.f;
        {
            const int p = tid & 7;
            for (int cl = tid >> 3; cl < 136; cl += 128) {
                const bool valid = (cl < w);
                const int j = js + (valid ? cl : 0);
                float T = 0.f;
                if (valid) {
                    for (int b2 = p; b2 < NBLK; b2 += 8)
                        T += __ldcg(&g_C[(size_t)b2 * Mm + j]);
                }
                T += __shfl_down_sync(0xffffffffu, T, 4, 8);
                T += __shfl_down_sync(0xffffffffu, T, 2, 8);
                T += __shfl_down_sync(0xffffffffu, T, 1, 8);
                if (p == 0 && valid) {
                    if (chk) errA += fabsf(__ldcg(&g_v[j]) * T - bm);
                    g_v[j] = bm / (T + EPSc);
                }
            }
        }
        if (chk) {
            #pragma unroll
            for (int o = 16; o > 0; o >>= 1)
                errA += __shfl_xor_sync(0xffffffffu, errA, o);
            if (tx == 0) s_wS[ty] = errA;
            __syncthreads();
            if (ty == 0) {
                float e2 = s_wS[tx];
                #pragma unroll
                for (int o = 16; o > 0; o >>= 1)
                    e2 += __shfl_xor_sync(0xffffffffu, e2, o);
                if (tx == 0) g_errP[bid] = e2;
            }
        }
        gridbar(&s_ep);

        if (chk) {                              // redundant uniform decide
            float e = (tid < NBLK) ? __ldcg(&g_errP[tid]) : 0.f;
            #pragma unroll
            for (int o = 16; o > 0; o >>= 1)
                e += __shfl_xor_sync(0xffffffffu, e, o);
            if (tx == 0) s_wS[ty] = e;
            __syncthreads();
            if (tid == 0) {
                float t2 = 0.f;
                #pragma unroll
                for (int q2 = 0; q2 < 32; ++q2) t2 += s_wS[q2];
                s_bc = t2;
            }
            __syncthreads();
            if (s_bc <= THR) {
                if (bid == 0) {
                    float l = (tid < NBLK) ? __ldcg(&g_lossP[tid]) : 0.f;
                    #pragma unroll
                    for (int o = 16; o > 0; o >>= 1)
                        l += __shfl_xor_sync(0xffffffffu, l, o);
                    __syncthreads();
                    if (tx == 0) s_wL[ty] = l;
                    __syncthreads();
                    if (ty == 0) {
                        float t3 = s_wL[tx];
                        #pragma unroll
                        for (int o = 16; o > 0; o >>= 1)
                            t3 += __shfl_xor_sync(0xffffffffu, t3, o);
                        if (tx == 0) out[0] = t3 * (-100.0f / ALPHA);
                    }
                }
                done = true;
            }
            __syncthreads();
        }
    }

    // Final arrive: last block resets ticket + barrier for the next replay.
    __syncthreads();
    if (tid == 0) {
        __threadfence();
        unsigned old = atomicAdd(&g_barcnt, 1u);
        if (old == s_ep + NBLK - 1) {
            atomicExch(&g_ticket, 0u);
            atomicExch(&g_barcnt, 0u);
        }
    }
}

extern "C" void kernel_launch(void* const* d_in, const int* in_sizes, int n_in,
                              void* d_out, int out_size) {
    const float* M = (const float*)d_in[0];
    float* out = (float*)d_out;
    sinkhorn_all<<<NBLK, NT>>>(M, out);
}

// round 15
// speedup vs baseline: 1.1174x; 1.1174x over previous
#include <cuda_runtime.h>

// M is 2000 x 20000 fp32 (fixed by setup_inputs).
#define Nn 2000
#define Mm 20000
#define ALPHA 20.0f
#define THR 0.005f
#define EPSc 1e-16f
#define NT 256
#define NBLK 740                 // 5 x 148 SMs: all blocks co-resident
// Phase A: 200 col-tiles (100 cols) x 20 row-chunks (100 rows), FORWARD
#define A_CT 200
#define A_TW 100
#define A_RC 20
#define A_TASKS (A_CT * A_RC)    // 4000
// Phase B: 500 row-groups (4 rows) x 10 col-slices (2000 cols), REVERSED
#define B_GRP 500
#define B_SL 10
#define B_SW 2000
#define B_TASKS (B_GRP * B_SL)   // 5000

// Static device scratch (no runtime allocation). No fp16 mirror of M:
// every pass recomputes e = exp(-20 m) from M; alternating sweep direction
// gives ~126 MB of L2 reuse between consecutive passes.
__device__ float g_u[Nn];
__device__ float g_v[Mm];
__device__ float g_PA[A_RC * Mm];          // K^T u partials (1.6 MB)
__device__ float g_SB[B_SL * Nn];          // K v partials
__device__ float g_LB[B_SL * Nn];          // K v m partials (loss integrand)
__device__ float g_lossR[Nn];              // u_i * sum_j e v m
__device__ float g_errT[A_CT];
__device__ int   g_cntA[A_CT];
__device__ int   g_cntB[B_GRP];
__device__ unsigned g_ticket = 0;
__device__ unsigned g_barcnt = 0;

__device__ __forceinline__ unsigned ldcg_u(const unsigned* p) {
    unsigned v;
    asm volatile("ld.global.cg.u32 %0, [%1];" : "=r"(v) : "l"(p));
    return v;
}

// Grid barrier: one arrival atomic per block; plain-L2-load polling.
__device__ __forceinline__ void gridbar(unsigned* eps) {
    __syncthreads();
    if (threadIdx.x == 0) {
        unsigned target = *eps + NBLK;
        __threadfence();                       // release
        atomicAdd(&g_barcnt, 1u);
        while (ldcg_u(&g_barcnt) < target) __nanosleep(64);
        __threadfence();                       // acquire
        *eps = target;
    }
    __syncthreads();
}

__global__ void __launch_bounds__(NT, 5)
sinkhorn_all(const float* __restrict__ M, float* __restrict__ out) {
    const int tid = threadIdx.x;
    const int bid = blockIdx.x;
    const int tx = tid & 31, ty = tid >> 5;
    // Phase-A map: thread owns 4 cols (fc) over 10 rows (row group rg)
    const int rg = tid / 25;                   // 0..9 valid when tid<250
    const int fc = tid - rg * 25;              // 0..24
    const bool actA = (tid < 250);

    __shared__ float s_u[Nn];                  // 8 KB
    __shared__ float s_rT[10][A_TW];           // 4 KB
    __shared__ float sA[NT];
    __shared__ float s_wS[8][4], s_wL[8][4];
    __shared__ float s_cbS[B_SL][4], s_cbL[B_SL][4];
    __shared__ int s_cur, s_next, s_comb;
    __shared__ unsigned s_ep;

    if (tid == 0) s_ep = 0;
    __syncthreads();

    const float bm = 1.0f / (float)Mm;
    const float am = 1.0f / (float)Nn;
    unsigned tbase = 0;
    bool conv = false;

    // Reference: err only updated at cpt==1 / cpt==51 -> exit only at
    // cpt in {1,51,100}. chk at t==2/t==52 uses v_{t-1}, K^T u_{t-1}.
    // Loss for state (u_t, v_t) is computed by phase B of iteration t
    // (m is in registers there: loss needs NO log and NO extra pass).
    for (int t = 1; t <= 100; ++t) {
        const bool chk = (t == 2) || (t == 52);

        // ---- Phase A (FORWARD rows): T = K^T u partials from M;
        //      last-arriver per col-tile computes v (+err at chk). ----
        if (t > 1) {
            for (int i = tid; i < Nn; i += NT) s_u[i] = __ldcg(&g_u[i]);
        } else {
            for (int i = tid; i < Nn; i += NT) s_u[i] = 1.0f;  // u0 via am at combine
        }
        if (tid == 0) s_cur = (int)(atomicAdd(&g_ticket, 1u) - tbase);
        __syncthreads();
        int cur = s_cur;
        while (cur < A_TASKS) {
            if (tid == 255) s_next = (int)(atomicAdd(&g_ticket, 1u) - tbase);
            const int rc = cur / A_CT, ct = cur - rc * A_CT;
            const int j0 = ct * A_TW;
            const int r0 = rc * 100 + rg * 10;
            if (actA) {
                const float4* Mp = (const float4*)(M + (size_t)r0 * Mm + j0 + fc * 4);
                float a0 = 0.f, a1 = 0.f, a2 = 0.f, a3 = 0.f;
                #pragma unroll
                for (int k = 0; k < 10; ++k) {
                    float4 m4 = Mp[(size_t)k * (Mm / 4)];
                    float ui = s_u[r0 + k];
                    a0 = fmaf(__expf(-ALPHA * m4.x), ui, a0);
                    a1 = fmaf(__expf(-ALPHA * m4.y), ui, a1);
                    a2 = fmaf(__expf(-ALPHA * m4.z), ui, a2);
                    a3 = fmaf(__expf(-ALPHA * m4.w), ui, a3);
                }
                s_rT[rg][fc * 4]     = a0;
                s_rT[rg][fc * 4 + 1] = a1;
                s_rT[rg][fc * 4 + 2] = a2;
                s_rT[rg][fc * 4 + 3] = a3;
            }
            __syncthreads();
            if (tid < A_TW) {                  // fixed-order 10-way reduce
                float T = 0.f;
                #pragma unroll
                for (int g = 0; g < 10; ++g) T += s_rT[g][tid];
                g_PA[rc * Mm + j0 + tid] = T;
            }
            __syncthreads();
            if (tid == 0) {
                __threadfence();               // release partials
                int old = atomicAdd(&g_cntA[ct], 1);
                if (old == A_RC - 1) { __threadfence(); s_comb = 1; }
                else s_comb = 0;
            }
            __syncthreads();
            if (s_comb) {                      // combine: v (+err at chk)
                float e = 0.f;
                if (tid < A_TW) {
                    const int j = j0 + tid;
                    float T = 0.f;
                    #pragma unroll
                    for (int rcq = 0; rcq < A_RC; ++rcq)
                        T += __ldcg(&g_PA[rcq * Mm + j]);
                    if (t == 1) T *= am;
                    if (chk) e = fabsf(__ldcg(&g_v[j]) * T - bm);
                    g_v[j] = bm / (T + EPSc);
                }
                if (tid == 0) g_cntA[ct] = 0;  // reset for next use
                if (chk) {
                    sA[tid] = e;
                    __syncthreads();
                    for (int o = NT / 2; o > 0; o >>= 1) {
                        if (tid < o) sA[tid] += sA[tid + o];
                        __syncthreads();
                    }
                    if (tid == 0) g_errT[ct] = sA[0];
                }
            }
            cur = s_next;
            __syncthreads();
        }
        tbase += A_TASKS + NBLK;
        gridbar(&s_ep);

        if (chk) {
            // Every block redundantly computes the stop decision (same
            // fixed-order sum -> identical result -> uniform break).
            sA[tid] = (tid < A_CT) ? __ldcg(&g_errT[tid]) : 0.f;
            __syncthreads();
            for (int o = NT / 2; o > 0; o >>= 1) {
                if (tid < o) sA[tid] += sA[tid + o];
                __syncthreads();
            }
            if (sA[0] <= THR) {
                if (bid == 0) {                // loss from the previous phase B
                    float l = 0.f;
                    for (int i = tid; i < Nn; i += NT) l += __ldcg(&g_lossR[i]);
                    __syncthreads();
                    sA[tid] = l;
                    __syncthreads();
                    for (int o = NT / 2; o > 0; o >>= 1) {
                        if (tid < o) sA[tid] += sA[tid + o];
                        __syncthreads();
                    }
                    if (tid == 0) out[0] = sA[0] * 100.0f;
                }
                conv = true;
                break;
            }
        }

        // ---- Phase B (REVERSED row-groups, L2 reuse of M from phase A):
        //      per-row S = sum e*v and L = sum e*v*m from M directly;
        //      10th slice combines u_r and g_lossR[r]. ----
        if (tid == 0) s_cur = (int)(atomicAdd(&g_ticket, 1u) - tbase);
        __syncthreads();
        int cur2 = s_cur;
        while (cur2 < B_TASKS) {
            if (tid == 255) s_next = (int)(atomicAdd(&g_ticket, 1u) - tbase);
            const int grp = (B_GRP - 1) - (cur2 / B_SL);   // reverse order
            const int sl = cur2 % B_SL;
            const int r0g = grp * 4;
            float S0 = 0.f, S1 = 0.f, S2 = 0.f, S3 = 0.f;
            float L0 = 0.f, L1 = 0.f, L2 = 0.f, L3 = 0.f;
            if (tid < 250) {
                const float4* Vp = (const float4*)(g_v + sl * B_SW);
                float4 va = __ldcg(&Vp[2 * tid]);
                float4 vb = __ldcg(&Vp[2 * tid + 1]);
                #define BROW(S, L, r) { \
                    const float4* Mp = (const float4*)(M + (size_t)(r0g + (r)) * Mm + sl * B_SW); \
                    float4 ma = Mp[2 * tid], mb = Mp[2 * tid + 1]; \
                    float p0 = __expf(-ALPHA * ma.x) * va.x; \
                    float p1 = __expf(-ALPHA * ma.y) * va.y; \
                    float p2 = __expf(-ALPHA * ma.z) * va.z; \
                    float p3 = __expf(-ALPHA * ma.w) * va.w; \
                    float p4 = __expf(-ALPHA * mb.x) * vb.x; \
                    float p5 = __expf(-ALPHA * mb.y) * vb.y; \
                    float p6 = __expf(-ALPHA * mb.z) * vb.z; \
                    float p7 = __expf(-ALPHA * mb.w) * vb.w; \
                    S += ((p0 + p1) + (p2 + p3)) + ((p4 + p5) + (p6 + p7)); \
                    L += ((p0 * ma.x + p1 * ma.y) + (p2 * ma.z + p3 * ma.w)) \
                       + ((p4 * mb.x + p5 * mb.y) + (p6 * mb.z + p7 * mb.w)); }
                BROW(S0, L0, 0) BROW(S1, L1, 1) BROW(S2, L2, 2) BROW(S3, L3, 3)
                #undef BROW
            }
            #pragma unroll
            for (int o = 16; o > 0; o >>= 1) {
                S0 += __shfl_xor_sync(0xffffffffu, S0, o);
                S1 += __shfl_xor_sync(0xffffffffu, S1, o);
                S2 += __shfl_xor_sync(0xffffffffu, S2, o);
                S3 += __shfl_xor_sync(0xffffffffu, S3, o);
                L0 += __shfl_xor_sync(0xffffffffu, L0, o);
                L1 += __shfl_xor_sync(0xffffffffu, L1, o);
                L2 += __shfl_xor_sync(0xffffffffu, L2, o);
                L3 += __shfl_xor_sync(0xffffffffu, L3, o);
            }
            if (tx == 0) {
                s_wS[ty][0] = S0; s_wS[ty][1] = S1; s_wS[ty][2] = S2; s_wS[ty][3] = S3;
                s_wL[ty][0] = L0; s_wL[ty][1] = L1; s_wL[ty][2] = L2; s_wL[ty][3] = L3;
            }
            __syncthreads();
            if (tid < 8) {                     // fixed-order 8-warp reduce
                const int d = tid & 3;
                float s = 0.f;
                if (tid < 4) {
                    #pragma unroll
                    for (int w2 = 0; w2 < 8; ++w2) s += s_wS[w2][d];
                    g_SB[sl * Nn + r0g + d] = s;
                } else {
                    #pragma unroll
                    for (int w2 = 0; w2 < 8; ++w2) s += s_wL[w2][d];
                    g_LB[sl * Nn + r0g + d] = s;
                }
            }
            __syncthreads();
            if (tid == 0) {
                __threadfence();               // release
                int old = atomicAdd(&g_cntB[grp], 1);
                if (old == B_SL - 1) { __threadfence(); s_comb = 1; }
                else s_comb = 0;
            }
            __syncthreads();
            if (s_comb) {                      // combine u + lossR for 4 rows
                if (tid < 40) {
                    const int p = tid >> 2, rl = tid & 3;
                    s_cbS[p][rl] = __ldcg(&g_SB[p * Nn + r0g + rl]);
                } else if (tid < 80) {
                    const int q = tid - 40, p = q >> 2, rl = q & 3;
                    s_cbL[p][rl] = __ldcg(&g_LB[p * Nn + r0g + rl]);
                }
                __syncthreads();
                if (tid < 4) {
                    float St = 0.f, Lt = 0.f;
                    #pragma unroll
                    for (int p = 0; p < B_SL; ++p) {
                        St += s_cbS[p][tid];
                        Lt += s_cbL[p][tid];
                    }
                    const float u = am / (St + EPSc);
                    g_u[r0g + tid] = u;
                    g_lossR[r0g + tid] = u * Lt;
                }
                if (tid == 0) g_cntB[grp] = 0; // reset for next use
            }
            cur2 = s_next;
            __syncthreads();
        }
        tbase += B_TASKS + NBLK;
        gridbar(&s_ep);
    }

    // Exit at t==100 without convergence: loss from the last phase B.
    if (!conv && bid == 0) {
        float l = 0.f;
        for (int i = tid; i < Nn; i += NT) l += __ldcg(&g_lossR[i]);
        sA[tid] = l;
        __syncthreads();
        for (int o = NT / 2; o > 0; o >>= 1) {
            if (tid < o) sA[tid] += sA[tid + o];
            __syncthreads();
        }
        if (tid == 0) out[0] = sA[0] * 100.0f;
    }

    // Final arrive: last block resets ticket + barrier for the next replay.
    __syncthreads();
    if (tid == 0) {
        __threadfence();
        unsigned old = atomicAdd(&g_barcnt, 1u);
        if (old == s_ep + NBLK - 1) {
            atomicExch(&g_ticket, 0u);
            atomicExch(&g_barcnt, 0u);
        }
    }
}

extern "C" void kernel_launch(void* const* d_in, const int* in_sizes, int n_in,
                              void* d_out, int out_size) {
    const float* M = (const float*)d_in[0];
    float* out = (float*)d_out;
    sinkhorn_all<<<NBLK, NT>>>(M, out);
}

// round 16
// speedup vs baseline: 1.3884x; 1.2425x over previous
#include <cuda_runtime.h>

// M is 2000 x 20000 fp32 (fixed by setup_inputs).
#define Nn 2000
#define Mm 20000
#define ALPHA 20.0f
#define THR 0.005f
#define EPSc 1e-16f
#define NT 1024
#define NBLK 148                 // one block per SM; all co-resident
#define NS4 5000                 // float4 column slots per row (20000 cols)
#define Q4LIM 904                // slot q=4 valid for tid < 904 (4096+904=5000)
#define SMEM_DYN (5 * 1024 * 16) // v staged as float4[5][1024] = 80 KB

// Static device scratch (no runtime allocation).
__device__ float4 g_C4[(size_t)NBLK * NS4];  // per-block column partials, 11.8 MB
__device__ float4 g_v4[NS4];
__device__ float g_errP[NBLK];
__device__ float g_lossP[NBLK];
__device__ unsigned g_barcnt = 0;

__device__ __forceinline__ unsigned ldcg_u(const unsigned* p) {
    unsigned v;
    asm volatile("ld.global.cg.u32 %0, [%1];" : "=r"(v) : "l"(p));
    return v;
}

// Grid barrier: 148 arrivals (one atomic per block), plain-L2-load polling.
__device__ __forceinline__ void gridbar(unsigned* eps) {
    __syncthreads();
    if (threadIdx.x == 0) {
        unsigned target = *eps + NBLK;
        __threadfence();                        // release
        atomicAdd(&g_barcnt, 1u);
        while (ldcg_u(&g_barcnt) < target) __nanosleep(64);
        __threadfence();                        // acquire
        *eps = target;
    }
    __syncthreads();
}

// Column merge: T_j = sum over 148 block partials; optionally x am (first
// pass, uniform u0) and err vs old v (chk). Writes new v. Fully static:
// block owns slots [ss, ss+ws); 8 lanes per slot; width-8 shuffles always
// executed by ALL lanes (uniform bound, predicated data).
__device__ __forceinline__ float merge_cols(int ss, int ws, int tid,
                                            bool first, bool chk,
                                            float am, float bm) {
    const int p = tid & 7;
    const int sl = tid >> 3;                    // 0..127 uniform; ws <= 34
    const bool valid = (sl < ws);
    const int s = ss + (valid ? sl : 0);
    float4 T = make_float4(0.f, 0.f, 0.f, 0.f);
    if (valid) {
        for (int b = p; b < NBLK; b += 8) {     // fixed order per lane
            float4 c = __ldcg(&g_C4[(size_t)b * NS4 + s]);
            T.x += c.x; T.y += c.y; T.z += c.z; T.w += c.w;
        }
    }
    #pragma unroll
    for (int o = 4; o > 0; o >>= 1) {
        T.x += __shfl_down_sync(0xffffffffu, T.x, o, 8);
        T.y += __shfl_down_sync(0xffffffffu, T.y, o, 8);
        T.z += __shfl_down_sync(0xffffffffu, T.z, o, 8);
        T.w += __shfl_down_sync(0xffffffffu, T.w, o, 8);
    }
    float errA = 0.f;
    if (p == 0 && valid) {
        if (first) { T.x *= am; T.y *= am; T.z *= am; T.w *= am; }
        if (chk) {
            float4 vo = __ldcg(&g_v4[s]);
            errA = fabsf(vo.x * T.x - bm) + fabsf(vo.y * T.y - bm)
                 + fabsf(vo.z * T.z - bm) + fabsf(vo.w * T.w - bm);
        }
        g_v4[s] = make_float4(bm / (T.x + EPSc), bm / (T.y + EPSc),
                              bm / (T.z + EPSc), bm / (T.w + EPSc));
    }
    return errA;
}

__global__ void __launch_bounds__(NT, 1)
sinkhorn_all(const float* __restrict__ M, float* __restrict__ out) {
    extern __shared__ float4 sv4[];             // v staging: [5][1024]
    __shared__ float s_w[2][32];                // double-buffered warp sums
    __shared__ float sA[NT];
    __shared__ unsigned s_ep;

    const int tid = threadIdx.x, bid = blockIdx.x;
    const int tx = tid & 31, ty = tid >> 5;
    // static rows: 76 blocks x 14 + 72 x 13 = 2000
    const int rs = bid * 13 + min(bid, 76);
    const int re = rs + 13 + (bid < 76 ? 1 : 0);
    // static merge strip: 116 blocks x 34 + 32 x 33 = 5000 slots
    const int ss = bid * 33 + min(bid, 116);
    const int ws = 33 + (bid < 116 ? 1 : 0);

    if (tid == 0) s_ep = 0;
    __syncthreads();
    const float bm = 1.0f / (float)Mm;
    const float am = 1.0f / (float)Nn;

    // ---- P1: per-block colsum(e) partials. Pure streaming: no shared, no
    //      syncs, no atomics. Rows FORWARD. ----
    {
        float4 CS[5];
        #pragma unroll
        for (int q = 0; q < 5; ++q) CS[q] = make_float4(0.f, 0.f, 0.f, 0.f);
        for (int r = rs; r < re; ++r) {
            const float4* Mp = (const float4*)(M + (size_t)r * Mm);
            #pragma unroll
            for (int q = 0; q < 5; ++q) {
                if (q < 4 || tid < Q4LIM) {
                    float4 m4 = __ldcg(Mp + tid + 1024 * q);
                    CS[q].x += __expf(-ALPHA * m4.x);
                    CS[q].y += __expf(-ALPHA * m4.y);
                    CS[q].z += __expf(-ALPHA * m4.z);
                    CS[q].w += __expf(-ALPHA * m4.w);
                }
            }
        }
        #pragma unroll
        for (int q = 0; q < 5; ++q)
            if (q < 4 || tid < Q4LIM)
                g_C4[(size_t)bid * NS4 + tid + 1024 * q] = CS[q];
    }
    gridbar(&s_ep);

    // ---- v1 = bm / (colsum * am + eps) ----
    merge_cols(ss, ws, tid, true, false, am, bm);
    gridbar(&s_ep);

    // Reference: err only *updated* at cpt==1 / cpt==51 -> exit only at cpt
    // in {1,51,100}. Fused pass k: u_k = am/(K v_k + eps) row-wise, and in
    // the SAME sweep accumulates C = per-block K^T u_k partials and the
    // loss integrand u*e*v*m (m is in registers: no log, no extra pass).
    bool done = false;
    for (int k = 1; k <= 100 && !done; ++k) {
        const bool chk = (k == 1) || (k == 51);

        // Stage v_k into shared (80 KB), coalesced.
        #pragma unroll
        for (int q = 0; q < 5; ++q)
            if (q < 4 || tid < Q4LIM)
                sv4[q * 1024 + tid] = __ldcg(&g_v4[tid + 1024 * q]);
        __syncthreads();

        float4 C[5];
        #pragma unroll
        for (int q = 0; q < 5; ++q) C[q] = make_float4(0.f, 0.f, 0.f, 0.f);
        float loss_acc = 0.f;

        for (int r = re - 1; r >= rs; --r) {    // REVERSE: L2 reuse from P1
            const float4* Mp = (const float4*)(M + (size_t)r * Mm);
            float4 e[5];
            float S = 0.f, Lp = 0.f;
            #pragma unroll
            for (int q = 0; q < 5; ++q) {
                if (q < 4 || tid < Q4LIM) {
                    float4 m4 = __ldcg(Mp + tid + 1024 * q);
                    float4 vq = sv4[q * 1024 + tid];
                    float4 eq;
                    eq.x = __expf(-ALPHA * m4.x);
                    eq.y = __expf(-ALPHA * m4.y);
                    eq.z = __expf(-ALPHA * m4.z);
                    eq.w = __expf(-ALPHA * m4.w);
                    float p0 = eq.x * vq.x, p1 = eq.y * vq.y;
                    float p2 = eq.z * vq.z, p3 = eq.w * vq.w;
                    S += (p0 + p1) + (p2 + p3);
                    Lp += (p0 * m4.x + p1 * m4.y) + (p2 * m4.z + p3 * m4.w);
                    e[q] = eq;
                } else {
                    e[q] = make_float4(0.f, 0.f, 0.f, 0.f);
                }
            }
            // Block reduce S: warp sums -> shared (row-parity buffer) ->
            // every warp redundantly reduces the 32 sums. ONE sync per row.
            #pragma unroll
            for (int o = 16; o > 0; o >>= 1)
                S += __shfl_xor_sync(0xffffffffu, S, o);
            if (tx == 0) s_w[r & 1][ty] = S;
            __syncthreads();
            float Sv = s_w[r & 1][tx];
            #pragma unroll
            for (int o = 16; o > 0; o >>= 1)
                Sv += __shfl_xor_sync(0xffffffffu, Sv, o);
            const float u = am / (Sv + EPSc);
            loss_acc = fmaf(u, Lp, loss_acc);
            #pragma unroll
            for (int q = 0; q < 5; ++q) {
                C[q].x = fmaf(u, e[q].x, C[q].x);
                C[q].y = fmaf(u, e[q].y, C[q].y);
                C[q].z = fmaf(u, e[q].z, C[q].z);
                C[q].w = fmaf(u, e[q].w, C[q].w);
            }
        }
        #pragma unroll
        for (int q = 0; q < 5; ++q)
            if (q < 4 || tid < Q4LIM)
                g_C4[(size_t)bid * NS4 + tid + 1024 * q] = C[q];
        // Per-block loss partial (fixed-order tree).
        sA[tid] = loss_acc;
        __syncthreads();
        for (int o = NT / 2; o > 0; o >>= 1) {
            if (tid < o) sA[tid] += sA[tid + o];
            __syncthreads();
        }
        if (tid == 0) g_lossP[bid] = sA[0];
        gridbar(&s_ep);

        if (k == 100) {                         // exit without convergence
            if (bid == 0) {
                sA[tid] = (tid < NBLK) ? __ldcg(&g_lossP[tid]) : 0.f;
                __syncthreads();
                for (int o = NT / 2; o > 0; o >>= 1) {
                    if (tid < o) sA[tid] += sA[tid + o];
                    __syncthreads();
                }
                if (tid == 0) out[0] = sA[0] * 100.0f;
            }
            done = true;
            continue;
        }

        // ---- Merge: T_j, err at chk (old v), write v_{k+1} ----
        float errA = merge_cols(ss, ws, tid, false, chk, am, bm);
        if (chk) {
            sA[tid] = errA;
            __syncthreads();
            for (int o = NT / 2; o > 0; o >>= 1) {
                if (tid < o) sA[tid] += sA[tid + o];
                __syncthreads();
            }
            if (tid == 0) g_errP[bid] = sA[0];
        }
        gridbar(&s_ep);

        if (chk) {                              // redundant uniform decide
            sA[tid] = (tid < NBLK) ? __ldcg(&g_errP[tid]) : 0.f;
            __syncthreads();
            for (int o = NT / 2; o > 0; o >>= 1) {
                if (tid < o) sA[tid] += sA[tid + o];
                __syncthreads();
            }
            const bool stop = (sA[0] <= THR);
            __syncthreads();
            if (stop) {
                if (bid == 0) {                 // loss uses (u_k, v_k) ✓
                    sA[tid] = (tid < NBLK) ? __ldcg(&g_lossP[tid]) : 0.f;
                    __syncthreads();
                    for (int o = NT / 2; o > 0; o >>= 1) {
                        if (tid < o) sA[tid] += sA[tid + o];
                        __syncthreads();
                    }
                    if (tid == 0) out[0] = sA[0] * 100.0f;
                }
                done = true;
            }
        }
    }

    // Final arrive: last block resets the barrier for the next graph replay.
    __syncthreads();
    if (tid == 0) {
        __threadfence();
        unsigned old = atomicAdd(&g_barcnt, 1u);
        if (old == s_ep + NBLK - 1) atomicExch(&g_barcnt, 0u);
    }
}

extern "C" void kernel_launch(void* const* d_in, const int* in_sizes, int n_in,
                              void* d_out, int out_size) {
    const float* M = (const float*)d_in[0];
    float* out = (float*)d_out;
    // Host-side attribute set (idempotent, not a stream op — capture-safe).
    cudaFuncSetAttribute(sinkhorn_all,
                         cudaFuncAttributeMaxDynamicSharedMemorySize, SMEM_DYN);
    sinkhorn_all<<<NBLK, NT, SMEM_DYN>>>(M, out);
}